// round 7
// baseline (speedup 1.0000x reference)
#include <cuda_runtime.h>
#include <cuda_fp16.h>
#include <math.h>
#include <stdint.h>

#define DIM   1152
#define HEADS 16
#define HD    72
#define HDE   73
#define HID   4608
#define HID2  9216
#define BB    2
#define NN    4096
#define MM    (BB*NN)        // 8192
#define TEMB6 (6*DIM)
#define KVS   (2*DIM)        // fused k|v row stride

// ---------------- scratch (device globals; no allocation) ----------------
__device__ __half g_xh[MM*DIM];
__device__ float  g_q[MM*DIM];
__device__ float  g_kvbuf[(size_t)MM*KVS];   // cols [0,1152)=k, [1152,2304)=v
__device__ __half g_attnh[MM*DIM];
__device__ float  g_h2[MM*DIM];
__device__ __half g_yh[(size_t)MM*HID2];
__device__ __half g_zh[(size_t)MM*HID];
__device__ float  g_kvp[8*BB*HEADS*HD*HDE];
__device__ float  g_kv[BB*HEADS*HD*HDE];
__device__ __half g_wq[DIM*DIM];
__device__ __half g_wkv[2*DIM*DIM];          // rows 0-1151 Wk, 1152-2303 Wv
__device__ __half g_wo[DIM*DIM];
__device__ __half g_winv[2*HID*DIM];
__device__ __half g_wpt[DIM*HID];

// ---------------- fused fp32 -> half conversion of ALL weights ----------------
#define S1   (DIM*DIM/4)          // 331776 float4s per DIMxDIM weight
#define SINV (2*HID*DIM/4)        // 2654208
#define SPT  (DIM*HID/4)          // 1327104
#define CVT_TOT (4*S1 + SINV + SPT)

__device__ __forceinline__ void cvt4(const float4* s, __half* d, int i) {
    float4 v = s[i];
    __half2 lo = __floats2half2_rn(v.x, v.y);
    __half2 hi = __floats2half2_rn(v.z, v.w);
    *(uint2*)(d + (size_t)i*4) = make_uint2(*(unsigned*)&lo, *(unsigned*)&hi);
}

__global__ void cvt_all_kernel(const float4* __restrict__ Wq,
                               const float4* __restrict__ Wk,
                               const float4* __restrict__ Wv,
                               const float4* __restrict__ Wo,
                               const float4* __restrict__ Winv,
                               const float4* __restrict__ Wpt)
{
    int i = blockIdx.x * 256 + threadIdx.x;
    if (i >= CVT_TOT) return;
    if (i < S1)            { cvt4(Wq, g_wq, i); return; }
    i -= S1;
    if (i < S1)            { cvt4(Wk, g_wkv, i); return; }
    i -= S1;
    if (i < S1)            { float4 v = Wv[i];
                             __half2 lo = __floats2half2_rn(v.x, v.y);
                             __half2 hi = __floats2half2_rn(v.z, v.w);
                             *(uint2*)(g_wkv + (size_t)DIM*DIM + (size_t)i*4) =
                                 make_uint2(*(unsigned*)&lo, *(unsigned*)&hi);
                             return; }
    i -= S1;
    if (i < S1)            { cvt4(Wo, g_wo, i); return; }
    i -= S1;
    if (i < SINV)          { cvt4(Winv, g_winv, i); return; }
    i -= SINV;
    cvt4(Wpt, g_wpt, i);
}

// ---------------- adaLN modulation + RMSNorm -> half ----------------
__global__ void __launch_bounds__(288) modrms_kernel(
    const float* __restrict__ in, const float* __restrict__ temb,
    const float* __restrict__ sst, __half* __restrict__ out, int idx0)
{
    int row = blockIdx.x;
    int b   = row >> 12;
    const float* ip = in + (size_t)row*DIM;
    int d = threadIdx.x * 4;
    float4 h = *(const float4*)(ip + d);
    float ss = h.x*h.x + h.y*h.y + h.z*h.z + h.w*h.w;
    #pragma unroll
    for (int o = 16; o > 0; o >>= 1) ss += __shfl_down_sync(0xffffffffu, ss, o);
    __shared__ float red[9];
    int lane = threadIdx.x & 31, wid = threadIdx.x >> 5;
    if (lane == 0) red[wid] = ss;
    __syncthreads();
    if (threadIdx.x == 0) {
        float t = 0.f;
        #pragma unroll
        for (int i = 0; i < 9; i++) t += red[i];
        red[0] = rsqrtf(t * (1.0f/DIM) + 1e-6f);
    }
    __syncthreads();
    float r = red[0];
    const float* tb = temb + b*TEMB6;
    float4 sh, sc;
    {
        const float* s0 = sst + idx0*DIM + d;
        const float* t0 = tb  + idx0*DIM + d;
        const float* s1 = sst + (idx0+1)*DIM + d;
        const float* t1 = tb  + (idx0+1)*DIM + d;
        sh = make_float4(s0[0]+t0[0], s0[1]+t0[1], s0[2]+t0[2], s0[3]+t0[3]);
        sc = make_float4(s1[0]+t1[0], s1[1]+t1[1], s1[2]+t1[2], s1[3]+t1[3]);
    }
    __half2 o0 = __floats2half2_rn(h.x*r*(1.f+sc.x) + sh.x, h.y*r*(1.f+sc.y) + sh.y);
    __half2 o1 = __floats2half2_rn(h.z*r*(1.f+sc.z) + sh.z, h.w*r*(1.f+sc.w) + sh.w);
    *(uint2*)(out + (size_t)row*DIM + d) = make_uint2(*(unsigned*)&o0, *(unsigned*)&o1);
}

// ---------------- fp16 tensor-core NT GEMM with fused epilogues -------------
// C[M,Ntot] = A[M,K](half) * Bw[Ntot,K](half)^T, fp32 accum
// EPI: 0 relu(acc+bias)->f32, 1 acc+bias->f32, 2 gate_msa*(acc+bias)+extra->f32,
//      3 silu(acc+bias)->half, 4 extra + gate_mlp*acc->f32,
//      5 fused k|v: n<DIM relu(acc+biasA[n]) else acc+biasB[n-DIM] ->f32
#define BM 128
#define BN 128
#define BKG 32
#define BKP 40   // half elems per smem row (32 + 8 pad)

#define CP16(dst, src) \
    asm volatile("cp.async.cg.shared.global [%0], [%1], 16;" \
        :: "r"((unsigned)__cvta_generic_to_shared(dst)), "l"(src))

__device__ __forceinline__ void mma_f16(float c[4], const unsigned a[4], const unsigned b[2]) {
    asm volatile(
        "mma.sync.aligned.m16n8k16.row.col.f32.f16.f16.f32 "
        "{%0,%1,%2,%3}, {%4,%5,%6,%7}, {%8,%9}, {%0,%1,%2,%3};\n"
        : "+f"(c[0]), "+f"(c[1]), "+f"(c[2]), "+f"(c[3])
        : "r"(a[0]), "r"(a[1]), "r"(a[2]), "r"(a[3]), "r"(b[0]), "r"(b[1]));
}

template<int EPI, typename OutT>
__global__ void __launch_bounds__(256, 2) gemm_f16(
    const __half* __restrict__ A, const __half* __restrict__ Bw,
    const float* __restrict__ bias, const float* __restrict__ bias2,
    OutT* __restrict__ C, int K, int Ntot,
    const float* __restrict__ extra,
    const float* __restrict__ temb, const float* __restrict__ sst, int gidx)
{
    __shared__ __half Asm[2][BM][BKP];
    __shared__ __half Bsm[2][BN][BKP];

    const int m0 = blockIdx.y * BM, n0 = blockIdx.x * BN;
    const int tid = threadIdx.x;
    const int lane = tid & 31, warp = tid >> 5;
    const int wm = warp >> 2, wn = warp & 3;      // 2 x 4 warps -> 64x32 per warp
    const int ar = tid >> 2;                      // 0..63
    const int ac = (tid & 3) * 8;                 // 0,8,16,24 (halfs)

    const __half* Ap = A  + (size_t)(m0 + ar) * K + ac;
    const __half* Bp = Bw + (size_t)(n0 + ar) * K + ac;

    float acc[4][4][4];
    #pragma unroll
    for (int i = 0; i < 4; i++)
        #pragma unroll
        for (int j = 0; j < 4; j++)
            #pragma unroll
            for (int q = 0; q < 4; q++) acc[i][j][q] = 0.f;

    const int KT = K / BKG;

    {
        #pragma unroll
        for (int r = 0; r < 2; r++) {
            CP16(&Asm[0][ar + r*64][ac], Ap + (size_t)r*64*K);
            CP16(&Bsm[0][ar + r*64][ac], Bp + (size_t)r*64*K);
        }
        asm volatile("cp.async.commit_group;");
    }

    const int rr = lane >> 2, cc = lane & 3;

    for (int kt = 0; kt < KT; kt++) {
        int buf = kt & 1;
        if (kt + 1 < KT) {
            int nb = buf ^ 1;
            size_t off = (size_t)(kt + 1) * BKG;
            #pragma unroll
            for (int r = 0; r < 2; r++) {
                CP16(&Asm[nb][ar + r*64][ac], Ap + (size_t)r*64*K + off);
                CP16(&Bsm[nb][ar + r*64][ac], Bp + (size_t)r*64*K + off);
            }
            asm volatile("cp.async.commit_group;");
            asm volatile("cp.async.wait_group 1;");
        } else {
            asm volatile("cp.async.wait_group 0;");
        }
        __syncthreads();

        #pragma unroll
        for (int ks = 0; ks < 2; ks++) {
            int k0 = ks * 16;
            unsigned a[4][4], b[4][2];
            #pragma unroll
            for (int mt = 0; mt < 4; mt++) {
                int rb = wm*64 + mt*16;
                a[mt][0] = *(const unsigned*)&Asm[buf][rb+rr  ][k0 + cc*2    ];
                a[mt][1] = *(const unsigned*)&Asm[buf][rb+rr+8][k0 + cc*2    ];
                a[mt][2] = *(const unsigned*)&Asm[buf][rb+rr  ][k0 + cc*2 + 8];
                a[mt][3] = *(const unsigned*)&Asm[buf][rb+rr+8][k0 + cc*2 + 8];
            }
            #pragma unroll
            for (int nt = 0; nt < 4; nt++) {
                int cb = wn*32 + nt*8;
                b[nt][0] = *(const unsigned*)&Bsm[buf][cb+rr][k0 + cc*2    ];
                b[nt][1] = *(const unsigned*)&Bsm[buf][cb+rr][k0 + cc*2 + 8];
            }
            #pragma unroll
            for (int mt = 0; mt < 4; mt++)
                #pragma unroll
                for (int nt = 0; nt < 4; nt++)
                    mma_f16(acc[mt][nt], a[mt], b[nt]);
        }
        __syncthreads();
    }

    // epilogue
    #pragma unroll
    for (int mt = 0; mt < 4; mt++) {
        #pragma unroll
        for (int half_ = 0; half_ < 2; half_++) {
            int m = m0 + wm*64 + mt*16 + rr + half_*8;
            int bidx = m >> 12;
            #pragma unroll
            for (int nt = 0; nt < 4; nt++) {
                int n = n0 + wn*32 + nt*8 + cc*2;
                float v0 = acc[mt][nt][half_*2+0];
                float v1 = acc[mt][nt][half_*2+1];
                if (EPI == 0) {
                    v0 += bias[n];   v0 = v0 > 0.f ? v0 : 0.f;
                    v1 += bias[n+1]; v1 = v1 > 0.f ? v1 : 0.f;
                } else if (EPI == 1) {
                    v0 += bias[n]; v1 += bias[n+1];
                } else if (EPI == 2) {
                    v0 += bias[n]; v1 += bias[n+1];
                    float g0 = sst[gidx*DIM + n]   + temb[bidx*TEMB6 + gidx*DIM + n];
                    float g1 = sst[gidx*DIM + n+1] + temb[bidx*TEMB6 + gidx*DIM + n+1];
                    v0 = g0 * v0 + extra[(size_t)m*DIM + n];
                    v1 = g1 * v1 + extra[(size_t)m*DIM + n+1];
                } else if (EPI == 3) {
                    v0 += bias[n];   v0 = v0 / (1.f + expf(-v0));
                    v1 += bias[n+1]; v1 = v1 / (1.f + expf(-v1));
                } else if (EPI == 4) {
                    float g0 = sst[gidx*DIM + n]   + temb[bidx*TEMB6 + gidx*DIM + n];
                    float g1 = sst[gidx*DIM + n+1] + temb[bidx*TEMB6 + gidx*DIM + n+1];
                    v0 = extra[(size_t)m*DIM + n]   + g0 * v0;
                    v1 = extra[(size_t)m*DIM + n+1] + g1 * v1;
                } else if (EPI == 5) {
                    if (n < DIM) {
                        v0 += bias[n];   v0 = v0 > 0.f ? v0 : 0.f;
                        v1 += bias[n+1]; v1 = v1 > 0.f ? v1 : 0.f;
                    } else {
                        v0 += bias2[n - DIM];
                        v1 += bias2[n - DIM + 1];
                    }
                }
                if (sizeof(OutT) == 4) {
                    *(float2*)((float*)C + (size_t)m*Ntot + n) = make_float2(v0, v1);
                } else {
                    __half2 hv = __floats2half2_rn(v0, v1);
                    *(unsigned*)((__half*)C + (size_t)m*Ntot + n) = *(unsigned*)&hv;
                }
            }
        }
    }
}

// ---------------- kv = sum_n k (x) [v,1]  (split over 8 N-chunks) -----------
// reads fused kvbuf: row stride KVS, k at col h*HD, v at col DIM + h*HD
__global__ void __launch_bounds__(264) kv_kernel(const float* __restrict__ KV)
{
    int bh = blockIdx.x;
    int b = bh >> 4, h = bh & 15;
    int chunk = blockIdx.y;
    __shared__ float ks[8][72];
    __shared__ float vs[8][80];
    int tid = threadIdx.x;
    if (tid < 8*7) vs[tid/7][73 + tid%7] = 0.f;
    int d0 = (tid % 24) * 3;
    int e0 = (tid / 24) * 7;
    float acc[3][7];
    #pragma unroll
    for (int i = 0; i < 3; i++)
        #pragma unroll
        for (int j = 0; j < 7; j++) acc[i][j] = 0.f;

    const float* kbase = KV + (size_t)(b*NN)*KVS + h*HD;
    const float* vbase = KV + (size_t)(b*NN)*KVS + DIM + h*HD;
    int nstart = chunk * 512;

    for (int nn = 0; nn < 512; nn += 8) {
        __syncthreads();
        for (int i = tid; i < 8*72; i += 264) {
            int r = i / 72, d = i - r*72;
            ks[r][d] = kbase[(size_t)(nstart+nn+r)*KVS + d];
        }
        for (int i = tid; i < 8*73; i += 264) {
            int r = i / 73, e = i - r*73;
            vs[r][e] = (e < 72) ? vbase[(size_t)(nstart+nn+r)*KVS + e] : 1.0f;
        }
        __syncthreads();
        #pragma unroll
        for (int r = 0; r < 8; r++) {
            float kk[3], vv[7];
            #pragma unroll
            for (int i = 0; i < 3; i++) kk[i] = ks[r][d0+i];
            #pragma unroll
            for (int j = 0; j < 7; j++) vv[j] = vs[r][e0+j];
            #pragma unroll
            for (int i = 0; i < 3; i++)
                #pragma unroll
                for (int j = 0; j < 7; j++) acc[i][j] += kk[i]*vv[j];
        }
    }
    float* outp = g_kvp + ((size_t)chunk * 32 + bh) * (HD*HDE);
    #pragma unroll
    for (int i = 0; i < 3; i++)
        #pragma unroll
        for (int j = 0; j < 7; j++) {
            int e = e0 + j;
            if (e < HDE) outp[(d0+i)*HDE + e] = acc[i][j];
        }
}

__global__ void kv_reduce_kernel()
{
    int j = blockIdx.x * 256 + threadIdx.x;
    const int TOT = BB*HEADS*HD*HDE;
    if (j >= TOT) return;
    float s = 0.f;
    #pragma unroll
    for (int c = 0; c < 8; c++) s += g_kvp[(size_t)c*TOT + j];
    g_kv[j] = s;
}

// ---------------- out = (q . kv), numerator/denominator -> half -------------
__global__ void __launch_bounds__(320) attn_apply_kernel(
    const float* __restrict__ Q, __half* __restrict__ attn)
{
    int bh = blockIdx.x;
    int b = bh >> 4, h = bh & 15;
    int n0 = blockIdx.y * 64;
    __shared__ float kvs[72][80];
    __shared__ float qs[64][72];
    int tid = threadIdx.y * 80 + threadIdx.x;

    const float* kvsrc = g_kv + (size_t)bh * (HD*HDE);
    for (int i = tid; i < HD*HDE; i += 320) kvs[i/HDE][i%HDE] = kvsrc[i];
    const float* qbase = Q + (size_t)(b*NN + n0)*DIM + h*HD;
    for (int i = tid; i < 64*72; i += 320) {
        int r = i / 72, d = i - r*72;
        qs[r][d] = qbase[(size_t)r*DIM + d];
    }
    __syncthreads();

    int e = threadIdx.x, ty = threadIdx.y;
    float acc[16];
    #pragma unroll
    for (int r = 0; r < 16; r++) acc[r] = 0.f;
    if (e < HDE) {
        for (int d = 0; d < 72; d++) {
            float kvv = kvs[d][e];
            #pragma unroll
            for (int r = 0; r < 16; r++) acc[r] += qs[ty + r*4][d] * kvv;
        }
    }
    __syncthreads();
    float* outs = &kvs[0][0];
    if (e < HDE) {
        #pragma unroll
        for (int r = 0; r < 16; r++) outs[(ty + r*4)*80 + e] = acc[r];
    }
    __syncthreads();
    __half* ob = attn + (size_t)(b*NN + n0)*DIM + h*HD;
    for (int i = tid; i < 64*72; i += 320) {
        int r = i / 72, d = i - r*72;
        ob[(size_t)r*DIM + d] = __float2half_rn(
            outs[r*80 + d] / (outs[r*80 + 72] + 1e-15f));
    }
}

// ---------------- depthwise conv (k=3, pad 1) + GLU, half2-vectorized -------
__global__ void dwglu_kernel(const __half* __restrict__ Y,
                             const float* __restrict__ Wdw,
                             const float* __restrict__ bdw,
                             __half* __restrict__ Z)
{
    int idx2 = blockIdx.x * 256 + threadIdx.x;
    const int TOT2 = BB*NN*HID/2;
    if (idx2 >= TOT2) return;
    const int H2 = HID/2;
    int c2 = idx2 % H2;
    int c  = c2 * 2;
    int n = (idx2 / H2) & (NN-1);
    int b = idx2 / (H2*NN);

    float xg0 = bdw[c],       xg1 = bdw[c+1];
    float gt0 = bdw[c+HID],   gt1 = bdw[c+HID+1];
    #pragma unroll
    for (int t = 0; t < 3; t++) {
        int nn = n + t - 1;
        if (nn >= 0 && nn < NN) {
            const __half* yr = Y + (size_t)(b*NN + nn) * HID2;
            __half2 ya = *(const __half2*)(yr + c);
            __half2 yg = *(const __half2*)(yr + c + HID);
            xg0 += __low2float(ya)  * Wdw[c*3 + t];
            xg1 += __high2float(ya) * Wdw[(c+1)*3 + t];
            gt0 += __low2float(yg)  * Wdw[(c+HID)*3 + t];
            gt1 += __high2float(yg) * Wdw[(c+HID+1)*3 + t];
        }
    }
    float s0 = gt0 / (1.f + expf(-gt0));
    float s1 = gt1 / (1.f + expf(-gt1));
    __half2 o = __floats2half2_rn(xg0 * s0, xg1 * s1);
    *(__half2*)(Z + (size_t)(b*NN + n)*HID + c) = o;
}

// ---------------- host launcher ----------------
extern "C" void kernel_launch(void* const* d_in, const int* in_sizes, int n_in,
                              void* d_out, int out_size)
{
    const float* hidden = (const float*)d_in[0];
    const float* temb   = (const float*)d_in[1];
    const float* sst    = (const float*)d_in[2];
    const float* Wq     = (const float*)d_in[3];
    const float* bq     = (const float*)d_in[4];
    const float* Wk     = (const float*)d_in[5];
    const float* bk     = (const float*)d_in[6];
    const float* Wv     = (const float*)d_in[7];
    const float* bv     = (const float*)d_in[8];
    const float* Wo     = (const float*)d_in[9];
    const float* bo     = (const float*)d_in[10];
    const float* W_inv  = (const float*)d_in[11];
    const float* b_inv  = (const float*)d_in[12];
    const float* W_dw   = (const float*)d_in[13];
    const float* b_dw   = (const float*)d_in[14];
    const float* W_pt   = (const float*)d_in[15];
    float* out = (float*)d_out;

    __half *xh, *attnh, *yh, *zh, *wq, *wkv, *wo, *winv, *wpt;
    float *q, *kvbuf, *h2;
    cudaGetSymbolAddress((void**)&xh,    g_xh);
    cudaGetSymbolAddress((void**)&q,     g_q);
    cudaGetSymbolAddress((void**)&kvbuf, g_kvbuf);
    cudaGetSymbolAddress((void**)&attnh, g_attnh);
    cudaGetSymbolAddress((void**)&h2,    g_h2);
    cudaGetSymbolAddress((void**)&yh,    g_yh);
    cudaGetSymbolAddress((void**)&zh,    g_zh);
    cudaGetSymbolAddress((void**)&wq,    g_wq);
    cudaGetSymbolAddress((void**)&wkv,   g_wkv);
    cudaGetSymbolAddress((void**)&wo,    g_wo);
    cudaGetSymbolAddress((void**)&winv,  g_winv);
    cudaGetSymbolAddress((void**)&wpt,   g_wpt);

    // launch 0: all weight conversions in one kernel
    cvt_all_kernel<<<(CVT_TOT + 255)/256, 256>>>(
        (const float4*)Wq, (const float4*)Wk, (const float4*)Wv,
        (const float4*)Wo, (const float4*)W_inv, (const float4*)W_pt);

    // launch 1: x = rms(hidden)*(1+scale_msa)+shift_msa -> half
    modrms_kernel<<<MM, 288>>>(hidden, temb, sst, xh, 0);

    // launch 2: fused k|v projection (N=2304)
    gemm_f16<5,float><<<dim3(KVS/BN, MM/BM), 256>>>(
        xh, wkv, bk, bv, kvbuf, DIM, KVS, nullptr, nullptr, nullptr, 0);

    // launch 3-4: kv accumulation + deterministic reduce
    kv_kernel<<<dim3(32, 8), 264>>>(kvbuf);
    kv_reduce_kernel<<<(BB*HEADS*HD*HDE + 255)/256, 256>>>();

    // launch 5: q projection (this is the launch ncu -s 5 profiles)
    gemm_f16<0,float><<<dim3(DIM/BN, MM/BM), 256>>>(
        xh, wq, bq, nullptr, q, DIM, DIM, nullptr, nullptr, nullptr, 0);

    // launch 6: out = q.kv, numerator/denominator -> half
    attn_apply_kernel<<<dim3(32, NN/64), dim3(80, 4)>>>(q, attnh);

    // launch 7: h2 = gate_msa*(attn@Wo^T + bo) + hidden -> f32
    gemm_f16<2,float><<<dim3(DIM/BN, MM/BM), 256>>>(
        attnh, wo, bo, nullptr, h2, DIM, DIM, hidden, temb, sst, 2);

    // launch 8: x = rms(h2)*(1+scale_mlp)+shift_mlp -> half
    modrms_kernel<<<MM, 288>>>(h2, temb, sst, xh, 3);

    // launch 9: y = silu(x@W_inv^T + b_inv) -> half
    gemm_f16<3,__half><<<dim3(HID2/BN, MM/BM), 256>>>(
        xh, winv, b_inv, nullptr, yh, DIM, HID2, nullptr, nullptr, nullptr, 0);

    // launch 10: depthwise conv + GLU -> half z
    dwglu_kernel<<<(BB*NN*HID/2 + 255)/256, 256>>>(yh, W_dw, b_dw, zh);

    // launch 11: out = h2 + gate_mlp*(z@W_pt^T) -> f32
    gemm_f16<4,float><<<dim3(DIM/BN, MM/BM), 256>>>(
        zh, wpt, nullptr, nullptr, out, HID, DIM, h2, temb, sst, 5);
}

// round 8
// speedup vs baseline: 1.5744x; 1.5744x over previous
#include <cuda_runtime.h>
#include <cuda_fp16.h>
#include <math.h>
#include <stdint.h>

#define DIM   1152
#define HEADS 16
#define HD    72
#define HDE   73
#define HID   4608
#define HID2  9216
#define BB    2
#define NN    4096
#define MM    (BB*NN)        // 8192
#define TEMB6 (6*DIM)
#define NCHUNK 64            // kv split-N chunks
#define CROWS  (NN/NCHUNK)   // 64 rows per chunk

// ---------------- scratch (device globals; no allocation) ----------------
__device__ __half g_xh[MM*DIM];
__device__ float  g_q[MM*DIM];
__device__ float  g_k[MM*DIM];
__device__ float  g_v[MM*DIM];
__device__ __half g_attnh[MM*DIM];
__device__ float  g_h2[MM*DIM];
__device__ __half g_yh[(size_t)MM*HID2];
__device__ __half g_zh[(size_t)MM*HID];
__device__ float  g_kvp[(size_t)NCHUNK*BB*HEADS*HD*HDE];
__device__ float  g_kv[BB*HEADS*HD*HDE];
__device__ __half g_wq[DIM*DIM];
__device__ __half g_wk[DIM*DIM];
__device__ __half g_wv[DIM*DIM];
__device__ __half g_wo[DIM*DIM];
__device__ __half g_winv[2*HID*DIM];
__device__ __half g_wpt[DIM*HID];

// ---------------- fp32 -> half weight conversion ----------------
__global__ void cvt_half_kernel(const float4* __restrict__ src,
                                __half* __restrict__ dst, int n4)
{
    int i = blockIdx.x * 256 + threadIdx.x;
    if (i < n4) {
        float4 v = src[i];
        __half2 lo = __floats2half2_rn(v.x, v.y);
        __half2 hi = __floats2half2_rn(v.z, v.w);
        *(uint2*)(dst + (size_t)i*4) = make_uint2(*(unsigned*)&lo, *(unsigned*)&hi);
    }
}

// ---------------- adaLN modulation + RMSNorm -> half ----------------
__global__ void __launch_bounds__(288) modrms_kernel(
    const float* __restrict__ in, const float* __restrict__ temb,
    const float* __restrict__ sst, __half* __restrict__ out, int idx0)
{
    int row = blockIdx.x;
    int b   = row >> 12;
    const float* ip = in + (size_t)row*DIM;
    int d = threadIdx.x * 4;
    float4 h = *(const float4*)(ip + d);
    float ss = h.x*h.x + h.y*h.y + h.z*h.z + h.w*h.w;
    #pragma unroll
    for (int o = 16; o > 0; o >>= 1) ss += __shfl_down_sync(0xffffffffu, ss, o);
    __shared__ float red[9];
    int lane = threadIdx.x & 31, wid = threadIdx.x >> 5;
    if (lane == 0) red[wid] = ss;
    __syncthreads();
    if (threadIdx.x == 0) {
        float t = 0.f;
        #pragma unroll
        for (int i = 0; i < 9; i++) t += red[i];
        red[0] = rsqrtf(t * (1.0f/DIM) + 1e-6f);
    }
    __syncthreads();
    float r = red[0];
    const float* tb = temb + b*TEMB6;
    float4 sh, sc;
    {
        const float* s0 = sst + idx0*DIM + d;
        const float* t0 = tb  + idx0*DIM + d;
        const float* s1 = sst + (idx0+1)*DIM + d;
        const float* t1 = tb  + (idx0+1)*DIM + d;
        sh = make_float4(s0[0]+t0[0], s0[1]+t0[1], s0[2]+t0[2], s0[3]+t0[3]);
        sc = make_float4(s1[0]+t1[0], s1[1]+t1[1], s1[2]+t1[2], s1[3]+t1[3]);
    }
    __half2 o0 = __floats2half2_rn(h.x*r*(1.f+sc.x) + sh.x, h.y*r*(1.f+sc.y) + sh.y);
    __half2 o1 = __floats2half2_rn(h.z*r*(1.f+sc.z) + sh.z, h.w*r*(1.f+sc.w) + sh.w);
    *(uint2*)(out + (size_t)row*DIM + d) = make_uint2(*(unsigned*)&o0, *(unsigned*)&o1);
}

// ---------------- fp16 tensor-core NT GEMM with fused epilogues -------------
// C[M,Ntot] = A[M,K](half) * Bw[Ntot,K](half)^T, fp32 accum
// EPI: 0 relu(acc+bias)->f32, 1 acc+bias->f32, 2 gate_msa*(acc+bias)+extra->f32,
//      3 silu(acc+bias)->half, 4 extra + gate_mlp*acc->f32
#define BM 128
#define BN 128
#define BKG 32
#define BKP 40   // half elems per smem row (32 + 8 pad)

#define CP16(dst, src) \
    asm volatile("cp.async.cg.shared.global [%0], [%1], 16;" \
        :: "r"((unsigned)__cvta_generic_to_shared(dst)), "l"(src))

__device__ __forceinline__ void mma_f16(float c[4], const unsigned a[4], const unsigned b[2]) {
    asm volatile(
        "mma.sync.aligned.m16n8k16.row.col.f32.f16.f16.f32 "
        "{%0,%1,%2,%3}, {%4,%5,%6,%7}, {%8,%9}, {%0,%1,%2,%3};\n"
        : "+f"(c[0]), "+f"(c[1]), "+f"(c[2]), "+f"(c[3])
        : "r"(a[0]), "r"(a[1]), "r"(a[2]), "r"(a[3]), "r"(b[0]), "r"(b[1]));
}

template<int EPI, typename OutT>
__global__ void __launch_bounds__(256, 2) gemm_f16(
    const __half* __restrict__ A, const __half* __restrict__ Bw,
    const float* __restrict__ bias, OutT* __restrict__ C,
    int K, int Ntot,
    const float* __restrict__ extra,
    const float* __restrict__ temb, const float* __restrict__ sst, int gidx)
{
    __shared__ __half Asm[2][BM][BKP];
    __shared__ __half Bsm[2][BN][BKP];

    const int m0 = blockIdx.y * BM, n0 = blockIdx.x * BN;
    const int tid = threadIdx.x;
    const int lane = tid & 31, warp = tid >> 5;
    const int wm = warp >> 2, wn = warp & 3;      // 2 x 4 warps -> 64x32 per warp
    const int ar = tid >> 2;                      // 0..63
    const int ac = (tid & 3) * 8;                 // 0,8,16,24 (halfs)

    const __half* Ap = A  + (size_t)(m0 + ar) * K + ac;
    const __half* Bp = Bw + (size_t)(n0 + ar) * K + ac;

    float acc[4][4][4];
    #pragma unroll
    for (int i = 0; i < 4; i++)
        #pragma unroll
        for (int j = 0; j < 4; j++)
            #pragma unroll
            for (int q = 0; q < 4; q++) acc[i][j][q] = 0.f;

    const int KT = K / BKG;

    {
        #pragma unroll
        for (int r = 0; r < 2; r++) {
            CP16(&Asm[0][ar + r*64][ac], Ap + (size_t)r*64*K);
            CP16(&Bsm[0][ar + r*64][ac], Bp + (size_t)r*64*K);
        }
        asm volatile("cp.async.commit_group;");
    }

    const int rr = lane >> 2, cc = lane & 3;

    for (int kt = 0; kt < KT; kt++) {
        int buf = kt & 1;
        if (kt + 1 < KT) {
            int nb = buf ^ 1;
            size_t off = (size_t)(kt + 1) * BKG;
            #pragma unroll
            for (int r = 0; r < 2; r++) {
                CP16(&Asm[nb][ar + r*64][ac], Ap + (size_t)r*64*K + off);
                CP16(&Bsm[nb][ar + r*64][ac], Bp + (size_t)r*64*K + off);
            }
            asm volatile("cp.async.commit_group;");
            asm volatile("cp.async.wait_group 1;");
        } else {
            asm volatile("cp.async.wait_group 0;");
        }
        __syncthreads();

        #pragma unroll
        for (int ks = 0; ks < 2; ks++) {
            int k0 = ks * 16;
            unsigned a[4][4], b[4][2];
            #pragma unroll
            for (int mt = 0; mt < 4; mt++) {
                int rb = wm*64 + mt*16;
                a[mt][0] = *(const unsigned*)&Asm[buf][rb+rr  ][k0 + cc*2    ];
                a[mt][1] = *(const unsigned*)&Asm[buf][rb+rr+8][k0 + cc*2    ];
                a[mt][2] = *(const unsigned*)&Asm[buf][rb+rr  ][k0 + cc*2 + 8];
                a[mt][3] = *(const unsigned*)&Asm[buf][rb+rr+8][k0 + cc*2 + 8];
            }
            #pragma unroll
            for (int nt = 0; nt < 4; nt++) {
                int cb = wn*32 + nt*8;
                b[nt][0] = *(const unsigned*)&Bsm[buf][cb+rr][k0 + cc*2    ];
                b[nt][1] = *(const unsigned*)&Bsm[buf][cb+rr][k0 + cc*2 + 8];
            }
            #pragma unroll
            for (int mt = 0; mt < 4; mt++)
                #pragma unroll
                for (int nt = 0; nt < 4; nt++)
                    mma_f16(acc[mt][nt], a[mt], b[nt]);
        }
        __syncthreads();
    }

    // epilogue
    #pragma unroll
    for (int mt = 0; mt < 4; mt++) {
        #pragma unroll
        for (int half_ = 0; half_ < 2; half_++) {
            int m = m0 + wm*64 + mt*16 + rr + half_*8;
            int bidx = m >> 12;
            #pragma unroll
            for (int nt = 0; nt < 4; nt++) {
                int n = n0 + wn*32 + nt*8 + cc*2;
                float v0 = acc[mt][nt][half_*2+0];
                float v1 = acc[mt][nt][half_*2+1];
                if (EPI == 0) {
                    v0 += bias[n];   v0 = v0 > 0.f ? v0 : 0.f;
                    v1 += bias[n+1]; v1 = v1 > 0.f ? v1 : 0.f;
                } else if (EPI == 1) {
                    v0 += bias[n]; v1 += bias[n+1];
                } else if (EPI == 2) {
                    v0 += bias[n]; v1 += bias[n+1];
                    float g0 = sst[gidx*DIM + n]   + temb[bidx*TEMB6 + gidx*DIM + n];
                    float g1 = sst[gidx*DIM + n+1] + temb[bidx*TEMB6 + gidx*DIM + n+1];
                    v0 = g0 * v0 + extra[(size_t)m*DIM + n];
                    v1 = g1 * v1 + extra[(size_t)m*DIM + n+1];
                } else if (EPI == 3) {
                    v0 += bias[n];   v0 = v0 / (1.f + expf(-v0));
                    v1 += bias[n+1]; v1 = v1 / (1.f + expf(-v1));
                } else if (EPI == 4) {
                    float g0 = sst[gidx*DIM + n]   + temb[bidx*TEMB6 + gidx*DIM + n];
                    float g1 = sst[gidx*DIM + n+1] + temb[bidx*TEMB6 + gidx*DIM + n+1];
                    v0 = extra[(size_t)m*DIM + n]   + g0 * v0;
                    v1 = extra[(size_t)m*DIM + n+1] + g1 * v1;
                }
                if (sizeof(OutT) == 4) {
                    *(float2*)((float*)C + (size_t)m*Ntot + n) = make_float2(v0, v1);
                } else {
                    __half2 hv = __floats2half2_rn(v0, v1);
                    *(unsigned*)((__half*)C + (size_t)m*Ntot + n) = *(unsigned*)&hv;
                }
            }
        }
    }
}

// ---------------- kv = sum_n k (x) [v,1]  (split over 64 N-chunks) ----------
__global__ void __launch_bounds__(264) kv_kernel(
    const float* __restrict__ Kq, const float* __restrict__ Vq)
{
    int bh = blockIdx.x;             // 0..31
    int b = bh >> 4, h = bh & 15;
    int chunk = blockIdx.y;          // 0..63
    __shared__ float ks[8][72];
    __shared__ float vs[8][80];
    int tid = threadIdx.x;
    if (tid < 8*7) vs[tid/7][73 + tid%7] = 0.f;
    int d0 = (tid % 24) * 3;
    int e0 = (tid / 24) * 7;
    float acc[3][7];
    #pragma unroll
    for (int i = 0; i < 3; i++)
        #pragma unroll
        for (int j = 0; j < 7; j++) acc[i][j] = 0.f;

    const float* kbase = Kq + (size_t)(b*NN)*DIM + h*HD;
    const float* vbase = Vq + (size_t)(b*NN)*DIM + h*HD;
    int nstart = chunk * CROWS;

    for (int nn = 0; nn < CROWS; nn += 8) {
        __syncthreads();
        for (int i = tid; i < 8*72; i += 264) {
            int r = i / 72, d = i - r*72;
            ks[r][d] = kbase[(size_t)(nstart+nn+r)*DIM + d];
        }
        for (int i = tid; i < 8*73; i += 264) {
            int r = i / 73, e = i - r*73;
            vs[r][e] = (e < 72) ? vbase[(size_t)(nstart+nn+r)*DIM + e] : 1.0f;
        }
        __syncthreads();
        #pragma unroll
        for (int r = 0; r < 8; r++) {
            float kk[3], vv[7];
            #pragma unroll
            for (int i = 0; i < 3; i++) kk[i] = ks[r][d0+i];
            #pragma unroll
            for (int j = 0; j < 7; j++) vv[j] = vs[r][e0+j];
            #pragma unroll
            for (int i = 0; i < 3; i++)
                #pragma unroll
                for (int j = 0; j < 7; j++) acc[i][j] += kk[i]*vv[j];
        }
    }
    float* outp = g_kvp + ((size_t)chunk * 32 + bh) * (HD*HDE);
    #pragma unroll
    for (int i = 0; i < 3; i++)
        #pragma unroll
        for (int j = 0; j < 7; j++) {
            int e = e0 + j;
            if (e < HDE) outp[(d0+i)*HDE + e] = acc[i][j];
        }
}

// deterministic fixed-order reduce of the 64 partials
__global__ void kv_reduce_kernel()
{
    int j = blockIdx.x * 256 + threadIdx.x;
    const int TOT = BB*HEADS*HD*HDE;
    if (j >= TOT) return;
    float s = 0.f;
    #pragma unroll 8
    for (int c = 0; c < NCHUNK; c++) s += g_kvp[(size_t)c*TOT + j];
    g_kv[j] = s;
}

// ---------------- out = (q . kv), numerator/denominator -> half -------------
__global__ void __launch_bounds__(320) attn_apply_kernel(
    const float* __restrict__ Q, __half* __restrict__ attn)
{
    int bh = blockIdx.x;
    int b = bh >> 4, h = bh & 15;
    int n0 = blockIdx.y * 64;
    __shared__ float kvs[72][80];
    __shared__ float qs[64][72];
    int tid = threadIdx.y * 80 + threadIdx.x;

    const float* kvsrc = g_kv + (size_t)bh * (HD*HDE);
    for (int i = tid; i < HD*HDE; i += 320) kvs[i/HDE][i%HDE] = kvsrc[i];
    const float* qbase = Q + (size_t)(b*NN + n0)*DIM + h*HD;
    for (int i = tid; i < 64*72; i += 320) {
        int r = i / 72, d = i - r*72;
        qs[r][d] = qbase[(size_t)r*DIM + d];
    }
    __syncthreads();

    int e = threadIdx.x, ty = threadIdx.y;
    float acc[16];
    #pragma unroll
    for (int r = 0; r < 16; r++) acc[r] = 0.f;
    if (e < HDE) {
        for (int d = 0; d < 72; d++) {
            float kvv = kvs[d][e];
            #pragma unroll
            for (int r = 0; r < 16; r++) acc[r] += qs[ty + r*4][d] * kvv;
        }
    }
    __syncthreads();
    float* outs = &kvs[0][0];
    if (e < HDE) {
        #pragma unroll
        for (int r = 0; r < 16; r++) outs[(ty + r*4)*80 + e] = acc[r];
    }
    __syncthreads();
    __half* ob = attn + (size_t)(b*NN + n0)*DIM + h*HD;
    for (int i = tid; i < 64*72; i += 320) {
        int r = i / 72, d = i - r*72;
        ob[(size_t)r*DIM + d] = __float2half_rn(
            outs[r*80 + d] / (outs[r*80 + 72] + 1e-15f));
    }
}

// ---------------- depthwise conv (k=3, pad 1) + GLU, half2-vectorized -------
__global__ void dwglu_kernel(const __half* __restrict__ Y,
                             const float* __restrict__ Wdw,
                             const float* __restrict__ bdw,
                             __half* __restrict__ Z)
{
    int idx2 = blockIdx.x * 256 + threadIdx.x;
    const int TOT2 = BB*NN*HID/2;
    if (idx2 >= TOT2) return;
    const int H2 = HID/2;
    int c2 = idx2 % H2;
    int c  = c2 * 2;
    int n = (idx2 / H2) & (NN-1);
    int b = idx2 / (H2*NN);

    float xg0 = bdw[c],       xg1 = bdw[c+1];
    float gt0 = bdw[c+HID],   gt1 = bdw[c+HID+1];
    #pragma unroll
    for (int t = 0; t < 3; t++) {
        int nn = n + t - 1;
        if (nn >= 0 && nn < NN) {
            const __half* yr = Y + (size_t)(b*NN + nn) * HID2;
            __half2 ya = *(const __half2*)(yr + c);
            __half2 yg = *(const __half2*)(yr + c + HID);
            xg0 += __low2float(ya)  * Wdw[c*3 + t];
            xg1 += __high2float(ya) * Wdw[(c+1)*3 + t];
            gt0 += __low2float(yg)  * Wdw[(c+HID)*3 + t];
            gt1 += __high2float(yg) * Wdw[(c+HID+1)*3 + t];
        }
    }
    float s0 = gt0 / (1.f + expf(-gt0));
    float s1 = gt1 / (1.f + expf(-gt1));
    __half2 o = __floats2half2_rn(xg0 * s0, xg1 * s1);
    *(__half2*)(Z + (size_t)(b*NN + n)*HID + c) = o;
}

// ---------------- host launcher ----------------
extern "C" void kernel_launch(void* const* d_in, const int* in_sizes, int n_in,
                              void* d_out, int out_size)
{
    const float* hidden = (const float*)d_in[0];
    const float* temb   = (const float*)d_in[1];
    const float* sst    = (const float*)d_in[2];
    const float* Wq     = (const float*)d_in[3];
    const float* bq     = (const float*)d_in[4];
    const float* Wk     = (const float*)d_in[5];
    const float* bk     = (const float*)d_in[6];
    const float* Wv     = (const float*)d_in[7];
    const float* bv     = (const float*)d_in[8];
    const float* Wo     = (const float*)d_in[9];
    const float* bo     = (const float*)d_in[10];
    const float* W_inv  = (const float*)d_in[11];
    const float* b_inv  = (const float*)d_in[12];
    const float* W_dw   = (const float*)d_in[13];
    const float* b_dw   = (const float*)d_in[14];
    const float* W_pt   = (const float*)d_in[15];
    float* out = (float*)d_out;

    __half *xh, *attnh, *yh, *zh, *wq, *wk, *wv, *wo, *winv, *wpt;
    float *q, *k, *v, *h2;
    cudaGetSymbolAddress((void**)&xh,    g_xh);
    cudaGetSymbolAddress((void**)&q,     g_q);
    cudaGetSymbolAddress((void**)&k,     g_k);
    cudaGetSymbolAddress((void**)&v,     g_v);
    cudaGetSymbolAddress((void**)&attnh, g_attnh);
    cudaGetSymbolAddress((void**)&h2,    g_h2);
    cudaGetSymbolAddress((void**)&yh,    g_yh);
    cudaGetSymbolAddress((void**)&zh,    g_zh);
    cudaGetSymbolAddress((void**)&wq,    g_wq);
    cudaGetSymbolAddress((void**)&wk,    g_wk);
    cudaGetSymbolAddress((void**)&wv,    g_wv);
    cudaGetSymbolAddress((void**)&wo,    g_wo);
    cudaGetSymbolAddress((void**)&winv,  g_winv);
    cudaGetSymbolAddress((void**)&wpt,   g_wpt);

    // 0) convert weights to half
    cvt_half_kernel<<<(DIM*DIM/4 + 255)/256, 256>>>((const float4*)Wq, wq, DIM*DIM/4);
    cvt_half_kernel<<<(DIM*DIM/4 + 255)/256, 256>>>((const float4*)Wk, wk, DIM*DIM/4);
    cvt_half_kernel<<<(DIM*DIM/4 + 255)/256, 256>>>((const float4*)Wv, wv, DIM*DIM/4);
    cvt_half_kernel<<<(DIM*DIM/4 + 255)/256, 256>>>((const float4*)Wo, wo, DIM*DIM/4);
    cvt_half_kernel<<<(2*HID*DIM/4 + 255)/256, 256>>>((const float4*)W_inv, winv, 2*HID*DIM/4);
    cvt_half_kernel<<<(DIM*HID/4 + 255)/256, 256>>>((const float4*)W_pt, wpt, DIM*HID/4);

    dim3 gq(DIM/BN, MM/BM);          // (9, 64)

    // 1) x = rms(hidden)*(1+scale_msa)+shift_msa  -> half
    modrms_kernel<<<MM, 288>>>(hidden, temb, sst, xh, 0);

    // 2) q,k,v projections (fp16 tensor cores, fp32 out)
    gemm_f16<0,float><<<gq, 256>>>(xh, wq, bq, q, DIM, DIM, nullptr, nullptr, nullptr, 0);
    gemm_f16<0,float><<<gq, 256>>>(xh, wk, bk, k, DIM, DIM, nullptr, nullptr, nullptr, 0);
    gemm_f16<1,float><<<gq, 256>>>(xh, wv, bv, v, DIM, DIM, nullptr, nullptr, nullptr, 0);

    // 3) kv accumulation (64 chunks) + deterministic reduce
    kv_kernel<<<dim3(32, NCHUNK), 264>>>(k, v);
    kv_reduce_kernel<<<(BB*HEADS*HD*HDE + 255)/256, 256>>>();

    // 4) out = q.kv, numerator/denominator -> half
    attn_apply_kernel<<<dim3(32, NN/64), dim3(80, 4)>>>(q, attnh);

    // 5) h2 = gate_msa*(attn@Wo^T + bo) + hidden -> f32
    gemm_f16<2,float><<<gq, 256>>>(attnh, wo, bo, h2, DIM, DIM, hidden, temb, sst, 2);

    // 6) x = rms(h2)*(1+scale_mlp)+shift_mlp -> half
    modrms_kernel<<<MM, 288>>>(h2, temb, sst, xh, 3);

    // 7) y = silu(x@W_inv^T + b_inv) -> half
    gemm_f16<3,__half><<<dim3(HID2/BN, MM/BM), 256>>>(xh, winv, b_inv, yh, DIM, HID2,
                                                      nullptr, nullptr, nullptr, 0);

    // 8) depthwise conv + GLU -> half z
    dwglu_kernel<<<(BB*NN*HID/2 + 255)/256, 256>>>(yh, W_dw, b_dw, zh);

    // 9) out = h2 + gate_mlp*(z@W_pt^T) -> f32
    gemm_f16<4,float><<<gq, 256>>>(zh, wpt, nullptr, out, HID, DIM, h2, temb, sst, 5);
}

// round 9
// speedup vs baseline: 1.5823x; 1.0050x over previous
#include <cuda_runtime.h>
#include <cuda_fp16.h>
#include <math.h>
#include <stdint.h>

#define DIM   1152
#define HEADS 16
#define HD    72
#define HDE   73
#define HID   4608
#define HID2  9216
#define BB    2
#define NN    4096
#define MM    (BB*NN)        // 8192
#define TEMB6 (6*DIM)
#define NCHUNK 64            // kv split-N chunks
#define CROWS  (NN/NCHUNK)   // 64 rows per chunk

// ---------------- scratch (device globals; no allocation) ----------------
__device__ __half g_xh[MM*DIM];
__device__ float  g_q[MM*DIM];
__device__ float  g_k[MM*DIM];
__device__ float  g_v[MM*DIM];
__device__ __half g_attnh[MM*DIM];
__device__ float  g_h2[MM*DIM];
__device__ __half g_yh[(size_t)MM*HID2];
__device__ __half g_zh[(size_t)MM*HID];
__device__ float  g_kvp[(size_t)NCHUNK*BB*HEADS*HD*HDE];
__device__ float  g_kv[BB*HEADS*HD*HDE];
__device__ __half g_wq[DIM*DIM];
__device__ __half g_wk[DIM*DIM];
__device__ __half g_wv[DIM*DIM];
__device__ __half g_wo[DIM*DIM];
__device__ __half g_winv[2*HID*DIM];
__device__ __half g_wpt[DIM*HID];

// ---------------- fused fp32 -> half conversion of ALL weights --------------
#define S1   (DIM*DIM/4)          // 331776
#define SINV (2*HID*DIM/4)        // 2654208
#define SPT  (DIM*HID/4)          // 1327104
#define CVT_TOT (4*S1 + SINV + SPT)

__device__ __forceinline__ void cvt4(const float4* __restrict__ s,
                                     __half* __restrict__ d, int i) {
    float4 v = s[i];
    __half2 lo = __floats2half2_rn(v.x, v.y);
    __half2 hi = __floats2half2_rn(v.z, v.w);
    *(uint2*)(d + (size_t)i*4) = make_uint2(*(unsigned*)&lo, *(unsigned*)&hi);
}

__global__ void cvt_all_kernel(const float4* __restrict__ Wq,
                               const float4* __restrict__ Wk,
                               const float4* __restrict__ Wv,
                               const float4* __restrict__ Wo,
                               const float4* __restrict__ Winv,
                               const float4* __restrict__ Wpt)
{
    int i = blockIdx.x * 256 + threadIdx.x;
    if (i >= CVT_TOT) return;
    if (i < S1)   { cvt4(Wq, g_wq, i); return; }
    i -= S1;
    if (i < S1)   { cvt4(Wk, g_wk, i); return; }
    i -= S1;
    if (i < S1)   { cvt4(Wv, g_wv, i); return; }
    i -= S1;
    if (i < S1)   { cvt4(Wo, g_wo, i); return; }
    i -= S1;
    if (i < SINV) { cvt4(Winv, g_winv, i); return; }
    i -= SINV;
    cvt4(Wpt, g_wpt, i);
}

// ---------------- adaLN modulation + RMSNorm -> half ----------------
__global__ void __launch_bounds__(288) modrms_kernel(
    const float* __restrict__ in, const float* __restrict__ temb,
    const float* __restrict__ sst, __half* __restrict__ out, int idx0)
{
    int row = blockIdx.x;
    int b   = row >> 12;
    const float* ip = in + (size_t)row*DIM;
    int d = threadIdx.x * 4;
    float4 h = *(const float4*)(ip + d);
    float ss = h.x*h.x + h.y*h.y + h.z*h.z + h.w*h.w;
    #pragma unroll
    for (int o = 16; o > 0; o >>= 1) ss += __shfl_down_sync(0xffffffffu, ss, o);
    __shared__ float red[9];
    int lane = threadIdx.x & 31, wid = threadIdx.x >> 5;
    if (lane == 0) red[wid] = ss;
    __syncthreads();
    if (threadIdx.x == 0) {
        float t = 0.f;
        #pragma unroll
        for (int i = 0; i < 9; i++) t += red[i];
        red[0] = rsqrtf(t * (1.0f/DIM) + 1e-6f);
    }
    __syncthreads();
    float r = red[0];
    const float* tb = temb + b*TEMB6;
    float4 sh, sc;
    {
        const float* s0 = sst + idx0*DIM + d;
        const float* t0 = tb  + idx0*DIM + d;
        const float* s1 = sst + (idx0+1)*DIM + d;
        const float* t1 = tb  + (idx0+1)*DIM + d;
        sh = make_float4(s0[0]+t0[0], s0[1]+t0[1], s0[2]+t0[2], s0[3]+t0[3]);
        sc = make_float4(s1[0]+t1[0], s1[1]+t1[1], s1[2]+t1[2], s1[3]+t1[3]);
    }
    __half2 o0 = __floats2half2_rn(h.x*r*(1.f+sc.x) + sh.x, h.y*r*(1.f+sc.y) + sh.y);
    __half2 o1 = __floats2half2_rn(h.z*r*(1.f+sc.z) + sh.z, h.w*r*(1.f+sc.w) + sh.w);
    *(uint2*)(out + (size_t)row*DIM + d) = make_uint2(*(unsigned*)&o0, *(unsigned*)&o1);
}

// ---------------- fp16 tensor-core NT GEMM with fused epilogues -------------
// C[M,Ntot] = A[M,K](half) * Bw[Ntot,K](half)^T, fp32 accum
// EPI: 0 relu(acc+bias)->f32, 1 acc+bias->f32, 2 gate_msa*(acc+bias)+extra->f32,
//      3 silu(acc+bias)->half, 4 extra + gate_mlp*acc->f32
#define BM 128
#define BN 128
#define BKG 32
#define BKP 40   // half elems per smem row (32 + 8 pad)

#define CP16(dst, src) \
    asm volatile("cp.async.cg.shared.global [%0], [%1], 16;" \
        :: "r"((unsigned)__cvta_generic_to_shared(dst)), "l"(src))

__device__ __forceinline__ void mma_f16(float c[4], const unsigned a[4], const unsigned b[2]) {
    asm volatile(
        "mma.sync.aligned.m16n8k16.row.col.f32.f16.f16.f32 "
        "{%0,%1,%2,%3}, {%4,%5,%6,%7}, {%8,%9}, {%0,%1,%2,%3};\n"
        : "+f"(c[0]), "+f"(c[1]), "+f"(c[2]), "+f"(c[3])
        : "r"(a[0]), "r"(a[1]), "r"(a[2]), "r"(a[3]), "r"(b[0]), "r"(b[1]));
}

template<int EPI, typename OutT>
__global__ void __launch_bounds__(256, 2) gemm_f16(
    const __half* __restrict__ A, const __half* __restrict__ Bw,
    const float* __restrict__ bias, OutT* __restrict__ C,
    int K, int Ntot,
    const float* __restrict__ extra,
    const float* __restrict__ temb, const float* __restrict__ sst, int gidx)
{
    __shared__ __half Asm[2][BM][BKP];
    __shared__ __half Bsm[2][BN][BKP];

    const int m0 = blockIdx.y * BM, n0 = blockIdx.x * BN;
    const int tid = threadIdx.x;
    const int lane = tid & 31, warp = tid >> 5;
    const int wm = warp >> 2, wn = warp & 3;      // 2 x 4 warps -> 64x32 per warp
    const int ar = tid >> 2;                      // 0..63
    const int ac = (tid & 3) * 8;                 // 0,8,16,24 (halfs)

    const __half* Ap = A  + (size_t)(m0 + ar) * K + ac;
    const __half* Bp = Bw + (size_t)(n0 + ar) * K + ac;

    float acc[4][4][4];
    #pragma unroll
    for (int i = 0; i < 4; i++)
        #pragma unroll
        for (int j = 0; j < 4; j++)
            #pragma unroll
            for (int q = 0; q < 4; q++) acc[i][j][q] = 0.f;

    const int KT = K / BKG;

    {
        #pragma unroll
        for (int r = 0; r < 2; r++) {
            CP16(&Asm[0][ar + r*64][ac], Ap + (size_t)r*64*K);
            CP16(&Bsm[0][ar + r*64][ac], Bp + (size_t)r*64*K);
        }
        asm volatile("cp.async.commit_group;");
    }

    const int rr = lane >> 2, cc = lane & 3;

    for (int kt = 0; kt < KT; kt++) {
        int buf = kt & 1;
        if (kt + 1 < KT) {
            int nb = buf ^ 1;
            size_t off = (size_t)(kt + 1) * BKG;
            #pragma unroll
            for (int r = 0; r < 2; r++) {
                CP16(&Asm[nb][ar + r*64][ac], Ap + (size_t)r*64*K + off);
                CP16(&Bsm[nb][ar + r*64][ac], Bp + (size_t)r*64*K + off);
            }
            asm volatile("cp.async.commit_group;");
            asm volatile("cp.async.wait_group 1;");
        } else {
            asm volatile("cp.async.wait_group 0;");
        }
        __syncthreads();

        #pragma unroll
        for (int ks = 0; ks < 2; ks++) {
            int k0 = ks * 16;
            unsigned a[4][4], b[4][2];
            #pragma unroll
            for (int mt = 0; mt < 4; mt++) {
                int rb = wm*64 + mt*16;
                a[mt][0] = *(const unsigned*)&Asm[buf][rb+rr  ][k0 + cc*2    ];
                a[mt][1] = *(const unsigned*)&Asm[buf][rb+rr+8][k0 + cc*2    ];
                a[mt][2] = *(const unsigned*)&Asm[buf][rb+rr  ][k0 + cc*2 + 8];
                a[mt][3] = *(const unsigned*)&Asm[buf][rb+rr+8][k0 + cc*2 + 8];
            }
            #pragma unroll
            for (int nt = 0; nt < 4; nt++) {
                int cb = wn*32 + nt*8;
                b[nt][0] = *(const unsigned*)&Bsm[buf][cb+rr][k0 + cc*2    ];
                b[nt][1] = *(const unsigned*)&Bsm[buf][cb+rr][k0 + cc*2 + 8];
            }
            #pragma unroll
            for (int mt = 0; mt < 4; mt++)
                #pragma unroll
                for (int nt = 0; nt < 4; nt++)
                    mma_f16(acc[mt][nt], a[mt], b[nt]);
        }
        __syncthreads();
    }

    // epilogue
    #pragma unroll
    for (int mt = 0; mt < 4; mt++) {
        #pragma unroll
        for (int half_ = 0; half_ < 2; half_++) {
            int m = m0 + wm*64 + mt*16 + rr + half_*8;
            int bidx = m >> 12;
            #pragma unroll
            for (int nt = 0; nt < 4; nt++) {
                int n = n0 + wn*32 + nt*8 + cc*2;
                float v0 = acc[mt][nt][half_*2+0];
                float v1 = acc[mt][nt][half_*2+1];
                if (EPI == 0) {
                    v0 += bias[n];   v0 = v0 > 0.f ? v0 : 0.f;
                    v1 += bias[n+1]; v1 = v1 > 0.f ? v1 : 0.f;
                } else if (EPI == 1) {
                    v0 += bias[n]; v1 += bias[n+1];
                } else if (EPI == 2) {
                    v0 += bias[n]; v1 += bias[n+1];
                    float g0 = sst[gidx*DIM + n]   + temb[bidx*TEMB6 + gidx*DIM + n];
                    float g1 = sst[gidx*DIM + n+1] + temb[bidx*TEMB6 + gidx*DIM + n+1];
                    v0 = g0 * v0 + extra[(size_t)m*DIM + n];
                    v1 = g1 * v1 + extra[(size_t)m*DIM + n+1];
                } else if (EPI == 3) {
                    v0 += bias[n];   v0 = v0 / (1.f + expf(-v0));
                    v1 += bias[n+1]; v1 = v1 / (1.f + expf(-v1));
                } else if (EPI == 4) {
                    float g0 = sst[gidx*DIM + n]   + temb[bidx*TEMB6 + gidx*DIM + n];
                    float g1 = sst[gidx*DIM + n+1] + temb[bidx*TEMB6 + gidx*DIM + n+1];
                    v0 = extra[(size_t)m*DIM + n]   + g0 * v0;
                    v1 = extra[(size_t)m*DIM + n+1] + g1 * v1;
                }
                if (sizeof(OutT) == 4) {
                    *(float2*)((float*)C + (size_t)m*Ntot + n) = make_float2(v0, v1);
                } else {
                    __half2 hv = __floats2half2_rn(v0, v1);
                    *(unsigned*)((__half*)C + (size_t)m*Ntot + n) = *(unsigned*)&hv;
                }
            }
        }
    }
}

// ---------------- kv = sum_n k (x) [v,1]  (split over 64 N-chunks) ----------
__global__ void __launch_bounds__(264) kv_kernel(
    const float* __restrict__ Kq, const float* __restrict__ Vq)
{
    int bh = blockIdx.x;             // 0..31
    int b = bh >> 4, h = bh & 15;
    int chunk = blockIdx.y;          // 0..63
    __shared__ float ks[8][72];
    __shared__ float vs[8][80];
    int tid = threadIdx.x;
    if (tid < 8*7) vs[tid/7][73 + tid%7] = 0.f;
    int d0 = (tid % 24) * 3;
    int e0 = (tid / 24) * 7;
    float acc[3][7];
    #pragma unroll
    for (int i = 0; i < 3; i++)
        #pragma unroll
        for (int j = 0; j < 7; j++) acc[i][j] = 0.f;

    const float* kbase = Kq + (size_t)(b*NN)*DIM + h*HD;
    const float* vbase = Vq + (size_t)(b*NN)*DIM + h*HD;
    int nstart = chunk * CROWS;

    for (int nn = 0; nn < CROWS; nn += 8) {
        __syncthreads();
        for (int i = tid; i < 8*72; i += 264) {
            int r = i / 72, d = i - r*72;
            ks[r][d] = kbase[(size_t)(nstart+nn+r)*DIM + d];
        }
        for (int i = tid; i < 8*73; i += 264) {
            int r = i / 73, e = i - r*73;
            vs[r][e] = (e < 72) ? vbase[(size_t)(nstart+nn+r)*DIM + e] : 1.0f;
        }
        __syncthreads();
        #pragma unroll
        for (int r = 0; r < 8; r++) {
            float kk[3], vv[7];
            #pragma unroll
            for (int i = 0; i < 3; i++) kk[i] = ks[r][d0+i];
            #pragma unroll
            for (int j = 0; j < 7; j++) vv[j] = vs[r][e0+j];
            #pragma unroll
            for (int i = 0; i < 3; i++)
                #pragma unroll
                for (int j = 0; j < 7; j++) acc[i][j] += kk[i]*vv[j];
        }
    }
    float* outp = g_kvp + ((size_t)chunk * 32 + bh) * (HD*HDE);
    #pragma unroll
    for (int i = 0; i < 3; i++)
        #pragma unroll
        for (int j = 0; j < 7; j++) {
            int e = e0 + j;
            if (e < HDE) outp[(d0+i)*HDE + e] = acc[i][j];
        }
}

// deterministic fixed-order reduce of the 64 partials
__global__ void kv_reduce_kernel()
{
    int j = blockIdx.x * 256 + threadIdx.x;
    const int TOT = BB*HEADS*HD*HDE;
    if (j >= TOT) return;
    float s = 0.f;
    #pragma unroll 8
    for (int c = 0; c < NCHUNK; c++) s += g_kvp[(size_t)c*TOT + j];
    g_kv[j] = s;
}

// ---------------- out = (q . kv), numerator/denominator -> half -------------
__global__ void __launch_bounds__(320) attn_apply_kernel(
    const float* __restrict__ Q, __half* __restrict__ attn)
{
    int bh = blockIdx.x;
    int b = bh >> 4, h = bh & 15;
    int n0 = blockIdx.y * 64;
    __shared__ float kvs[72][80];
    __shared__ float qs[64][72];
    int tid = threadIdx.y * 80 + threadIdx.x;

    const float* kvsrc = g_kv + (size_t)bh * (HD*HDE);
    for (int i = tid; i < HD*HDE; i += 320) kvs[i/HDE][i%HDE] = kvsrc[i];
    const float* qbase = Q + (size_t)(b*NN + n0)*DIM + h*HD;
    for (int i = tid; i < 64*72; i += 320) {
        int r = i / 72, d = i - r*72;
        qs[r][d] = qbase[(size_t)r*DIM + d];
    }
    __syncthreads();

    int e = threadIdx.x, ty = threadIdx.y;
    float acc[16];
    #pragma unroll
    for (int r = 0; r < 16; r++) acc[r] = 0.f;
    if (e < HDE) {
        for (int d = 0; d < 72; d++) {
            float kvv = kvs[d][e];
            #pragma unroll
            for (int r = 0; r < 16; r++) acc[r] += qs[ty + r*4][d] * kvv;
        }
    }
    __syncthreads();
    float* outs = &kvs[0][0];
    if (e < HDE) {
        #pragma unroll
        for (int r = 0; r < 16; r++) outs[(ty + r*4)*80 + e] = acc[r];
    }
    __syncthreads();
    __half* ob = attn + (size_t)(b*NN + n0)*DIM + h*HD;
    for (int i = tid; i < 64*72; i += 320) {
        int r = i / 72, d = i - r*72;
        ob[(size_t)r*DIM + d] = __float2half_rn(
            outs[r*80 + d] / (outs[r*80 + 72] + 1e-15f));
    }
}

// ---------------- depthwise conv (k=3, pad 1) + GLU, sliding window ---------
// Each thread owns one channel pair c, marches 32 n-rows; y read exactly once.
#define DW_ROWS 32
__global__ void __launch_bounds__(256) dwglu_kernel(
    const __half* __restrict__ Y, const float* __restrict__ Wdw,
    const float* __restrict__ bdw, __half* __restrict__ Z)
{
    const int H2 = HID/2;                       // 2304 channel pairs
    int c2 = blockIdx.x * 256 + threadIdx.x;    // channel pair id
    if (c2 >= H2) return;
    int c = c2 * 2;
    int strip = blockIdx.y;                     // 0..(BB*NN/DW_ROWS-1)
    int bn0 = strip * DW_ROWS;                  // global row
    int b = bn0 / NN;
    int n0 = bn0 - b * NN;                      // within-batch start row

    // dw weights for 2 channels x 2 halves
    float wx0[3], wx1[3], wg0[3], wg1[3];
    #pragma unroll
    for (int t = 0; t < 3; t++) {
        wx0[t] = Wdw[c*3 + t];        wx1[t] = Wdw[(c+1)*3 + t];
        wg0[t] = Wdw[(c+HID)*3 + t];  wg1[t] = Wdw[(c+HID+1)*3 + t];
    }
    float bx0 = bdw[c],     bx1 = bdw[c+1];
    float bg0 = bdw[c+HID], bg1 = bdw[c+HID+1];

    const __half* ya = Y + (size_t)(b*NN) * HID2 + c;        // x-half stream
    const __half* yg = ya + HID;                              // gate-half stream
    __half* zp = Z + (size_t)(b*NN + n0) * HID + c;

    // window registers: [0]=n-1, [1]=n, [2]=n+1 (as float2 pairs)
    float2 a_m1, a_0, g_m1, g_0;
    {
        // load row n0-1 (or zeros) and row n0
        if (n0 > 0) {
            __half2 t = *(const __half2*)(ya + (size_t)(n0-1)*HID2);
            a_m1 = __half22float2(t);
            t = *(const __half2*)(yg + (size_t)(n0-1)*HID2);
            g_m1 = __half22float2(t);
        } else { a_m1 = make_float2(0.f,0.f); g_m1 = make_float2(0.f,0.f); }
        __half2 t = *(const __half2*)(ya + (size_t)n0*HID2);
        a_0 = __half22float2(t);
        t = *(const __half2*)(yg + (size_t)n0*HID2);
        g_0 = __half22float2(t);
    }

    #pragma unroll 4
    for (int r = 0; r < DW_ROWS; r++) {
        int n = n0 + r;
        float2 a_p1, g_p1;
        if (n + 1 < NN) {
            __half2 t = *(const __half2*)(ya + (size_t)(n+1)*HID2);
            a_p1 = __half22float2(t);
            t = *(const __half2*)(yg + (size_t)(n+1)*HID2);
            g_p1 = __half22float2(t);
        } else { a_p1 = make_float2(0.f,0.f); g_p1 = make_float2(0.f,0.f); }

        float xg0 = bx0 + a_m1.x*wx0[0] + a_0.x*wx0[1] + a_p1.x*wx0[2];
        float xg1 = bx1 + a_m1.y*wx1[0] + a_0.y*wx1[1] + a_p1.y*wx1[2];
        float gt0 = bg0 + g_m1.x*wg0[0] + g_0.x*wg0[1] + g_p1.x*wg0[2];
        float gt1 = bg1 + g_m1.y*wg1[0] + g_0.y*wg1[1] + g_p1.y*wg1[2];
        float s0 = gt0 / (1.f + expf(-gt0));
        float s1 = gt1 / (1.f + expf(-gt1));
        __half2 o = __floats2half2_rn(xg0 * s0, xg1 * s1);
        *(__half2*)(zp + (size_t)r*HID) = o;

        a_m1 = a_0; a_0 = a_p1;
        g_m1 = g_0; g_0 = g_p1;
    }
}

// ---------------- host launcher ----------------
extern "C" void kernel_launch(void* const* d_in, const int* in_sizes, int n_in,
                              void* d_out, int out_size)
{
    const float* hidden = (const float*)d_in[0];
    const float* temb   = (const float*)d_in[1];
    const float* sst    = (const float*)d_in[2];
    const float* Wq     = (const float*)d_in[3];
    const float* bq     = (const float*)d_in[4];
    const float* Wk     = (const float*)d_in[5];
    const float* bk     = (const float*)d_in[6];
    const float* Wv     = (const float*)d_in[7];
    const float* bv     = (const float*)d_in[8];
    const float* Wo     = (const float*)d_in[9];
    const float* bo     = (const float*)d_in[10];
    const float* W_inv  = (const float*)d_in[11];
    const float* b_inv  = (const float*)d_in[12];
    const float* W_dw   = (const float*)d_in[13];
    const float* b_dw   = (const float*)d_in[14];
    const float* W_pt   = (const float*)d_in[15];
    float* out = (float*)d_out;

    __half *xh, *attnh, *yh, *zh, *wq, *wk, *wv, *wo, *winv, *wpt;
    float *q, *k, *v, *h2;
    cudaGetSymbolAddress((void**)&xh,    g_xh);
    cudaGetSymbolAddress((void**)&q,     g_q);
    cudaGetSymbolAddress((void**)&k,     g_k);
    cudaGetSymbolAddress((void**)&v,     g_v);
    cudaGetSymbolAddress((void**)&attnh, g_attnh);
    cudaGetSymbolAddress((void**)&h2,    g_h2);
    cudaGetSymbolAddress((void**)&yh,    g_yh);
    cudaGetSymbolAddress((void**)&zh,    g_zh);
    cudaGetSymbolAddress((void**)&wq,    g_wq);
    cudaGetSymbolAddress((void**)&wk,    g_wk);
    cudaGetSymbolAddress((void**)&wv,    g_wv);
    cudaGetSymbolAddress((void**)&wo,    g_wo);
    cudaGetSymbolAddress((void**)&winv,  g_winv);
    cudaGetSymbolAddress((void**)&wpt,   g_wpt);

    dim3 gq(DIM/BN, MM/BM);          // (9, 64)

    // launch 0: all weight conversions fused
    cvt_all_kernel<<<(CVT_TOT + 255)/256, 256>>>(
        (const float4*)Wq, (const float4*)Wk, (const float4*)Wv,
        (const float4*)Wo, (const float4*)W_inv, (const float4*)W_pt);

    // launch 1: x = rms(hidden)*(1+scale_msa)+shift_msa -> half
    modrms_kernel<<<MM, 288>>>(hidden, temb, sst, xh, 0);

    // launches 2,3: k,v projections
    gemm_f16<0,float><<<gq, 256>>>(xh, wk, bk, k, DIM, DIM, nullptr, nullptr, nullptr, 0);
    gemm_f16<1,float><<<gq, 256>>>(xh, wv, bv, v, DIM, DIM, nullptr, nullptr, nullptr, 0);

    // launch 4: kv accumulation (64 chunks)
    kv_kernel<<<dim3(32, NCHUNK), 264>>>(k, v);

    // launch 5: q projection  <-- ncu -s 5 profiles this GEMM
    gemm_f16<0,float><<<gq, 256>>>(xh, wq, bq, q, DIM, DIM, nullptr, nullptr, nullptr, 0);

    // launch 6: deterministic reduce
    kv_reduce_kernel<<<(BB*HEADS*HD*HDE + 255)/256, 256>>>();

    // launch 7: out = q.kv, numerator/denominator -> half
    attn_apply_kernel<<<dim3(32, NN/64), dim3(80, 4)>>>(q, attnh);

    // launch 8: h2 = gate_msa*(attn@Wo^T + bo) + hidden -> f32
    gemm_f16<2,float><<<gq, 256>>>(attnh, wo, bo, h2, DIM, DIM, hidden, temb, sst, 2);

    // launch 9: x = rms(h2)*(1+scale_mlp)+shift_mlp -> half
    modrms_kernel<<<MM, 288>>>(h2, temb, sst, xh, 3);

    // launch 10: y = silu(x@W_inv^T + b_inv) -> half
    gemm_f16<3,__half><<<dim3(HID2/BN, MM/BM), 256>>>(xh, winv, b_inv, yh, DIM, HID2,
                                                      nullptr, nullptr, nullptr, 0);

    // launch 11: depthwise conv + GLU (sliding window) -> half z
    dwglu_kernel<<<dim3((HID/2 + 255)/256, MM/DW_ROWS), 256>>>(yh, W_dw, b_dw, zh);

    // launch 12: out = h2 + gate_mlp*(z@W_pt^T) -> f32
    gemm_f16<4,float><<<gq, 256>>>(zh, wpt, nullptr, out, HID, DIM, h2, temb, sst, 5);
}